// round 2
// baseline (speedup 1.0000x reference)
#include <cuda_runtime.h>
#include <cuda_bf16.h>
#include <cstdint>

#define T_LEN 32768
#define HID   256
#define NI_   1024
#define OUT_  32

// ---------------- scratch (device globals: no allocation allowed) ----------------
__device__ float g_xg_f[(size_t)T_LEN * 1024];   // gate preacts, fwd dir (reused layer0/layer1)
__device__ float g_xg_b[(size_t)T_LEN * 1024];   // gate preacts, bwd dir
__device__ float g_h0[(size_t)T_LEN * 512];      // layer0 output [T, 2H]
__device__ float g_h1[(size_t)T_LEN * 512];      // layer1 output [T, 2H]

// ---------------- device helpers ----------------
__device__ __forceinline__ unsigned long long ffma2(unsigned long long a,
                                                    unsigned long long b,
                                                    unsigned long long c) {
    unsigned long long d;
    asm("fma.rn.f32x2 %0, %1, %2, %3;" : "=l"(d) : "l"(a), "l"(b), "l"(c));
    return d;
}

__device__ __forceinline__ float sigm(float x) { return 1.f / (1.f + __expf(-x)); }
__device__ __forceinline__ float tanh_fast(float x) {
    float a = fabsf(x);
    float e = __expf(-2.f * a);
    float t = (1.f - e) / (1.f + e);
    return copysignf(t, x);
}

__device__ __forceinline__ uint32_t smaddr(const void* p) {
    return (uint32_t)__cvta_generic_to_shared(p);
}
__device__ __forceinline__ void mbar_init(uint32_t a, uint32_t cnt) {
    asm volatile("mbarrier.init.shared.b64 [%0], %1;" :: "r"(a), "r"(cnt) : "memory");
}
__device__ __forceinline__ uint32_t mapa_sh(uint32_t a, uint32_t rank) {
    uint32_t r;
    asm("mapa.shared::cluster.u32 %0, %1, %2;" : "=r"(r) : "r"(a), "r"(rank));
    return r;
}
__device__ __forceinline__ void remote_store_arrive(uint32_t raddr, float v, uint32_t rmbar) {
    asm volatile("st.shared::cluster.b32 [%0], %1;"
                 :: "r"(raddr), "r"(__float_as_uint(v)) : "memory");
    asm volatile("mbarrier.arrive.release.cluster.shared::cluster.b64 _, [%0];"
                 :: "r"(rmbar) : "memory");
}
__device__ __forceinline__ void mbar_wait_cl(uint32_t addr, uint32_t parity) {
    asm volatile(
        "{\n\t.reg .pred P;\n"
        "LW_%=:\n\t"
        "mbarrier.try_wait.parity.acquire.cluster.shared::cta.b64 P, [%0], %1;\n\t"
        "@P bra LD_%=;\n\t"
        "bra LW_%=;\n"
        "LD_%=:\n\t}"
        :: "r"(addr), "r"(parity) : "memory");
}
__device__ __forceinline__ void cluster_sync_() {
    asm volatile("barrier.cluster.arrive.aligned;" ::: "memory");
    asm volatile("barrier.cluster.wait.aligned;" ::: "memory");
}

// =================================================================================
// Kernel 1: layer-0 input projection. xg[t][row] = x[t] . w_ih[row] + b_ih + b_hh
// x[t] = concat(Y[t], dT[t]) (D_IN=64). Tiles: 32 t x 128 cols per block.
// grid (8, 1024, 2), block 256.
// =================================================================================
__global__ void __launch_bounds__(256) xg0_kernel(
    const float* __restrict__ Y, const float* __restrict__ dT,
    const float* __restrict__ w_f, const float* __restrict__ bi_f, const float* __restrict__ bh_f,
    const float* __restrict__ w_b, const float* __restrict__ bi_b, const float* __restrict__ bh_b,
    float* __restrict__ out_f, float* __restrict__ out_b)
{
    __shared__ float xs[32][64];
    __shared__ float ws[64][128];
    const float* w  = blockIdx.z ? w_b  : w_f;
    const float* bi = blockIdx.z ? bi_b : bi_f;
    const float* bh = blockIdx.z ? bh_b : bh_f;
    float* out      = blockIdx.z ? out_b : out_f;

    const int tid = threadIdx.x;
    const int tbase = blockIdx.y * 32;
    const int cbase = blockIdx.x * 128;

    for (int i = tid; i < 32 * 64; i += 256) {
        int tt = i >> 6, k = i & 63;
        int t = tbase + tt;
        xs[tt][k] = (k < 63) ? Y[(size_t)t * 63 + k] : dT[t];
    }
    for (int i = tid; i < 128 * 64; i += 256) {
        int c = i >> 6, k = i & 63;   // consecutive i -> consecutive k: coalesced
        ws[k][c] = w[(size_t)(cbase + c) * 64 + k];
    }
    __syncthreads();

    const int c = tid & 127;
    const int tr0 = tid >> 7;
    const float bias = bi[cbase + c] + bh[cbase + c];
    for (int tt = tr0; tt < 32; tt += 2) {
        float acc = bias;
        #pragma unroll
        for (int k = 0; k < 64; k++) acc += xs[tt][k] * ws[k][c];
        out[(size_t)(tbase + tt) * 1024 + cbase + c] = acc;
    }
}

// =================================================================================
// Kernel 2: LSTM scan (one layer, both directions). Cluster of 8 CTAs per
// direction; grid 16 = 2 clusters. CTA `rank` owns hidden units
// [rank*32, rank*32+32) and computes all 4 gate rows for them locally.
// Per step: registers-resident W_hh MAC against SMEM h, gate nonlinearity on
// warp 0, h broadcast to all 8 CTAs via DSMEM + mbarrier (double-buffered).
// =================================================================================
__global__ void __launch_bounds__(256, 1) lstm_scan_kernel(
    const float* __restrict__ xg_f, const float* __restrict__ xg_b,
    const float* __restrict__ whh_f, const float* __restrict__ whh_b,
    float* __restrict__ h_out)
{
    __shared__ __align__(16) unsigned long long h_sh[2][128]; // h as f32x2 pairs, double buffered
    __shared__ float gates_sh[128];
    __shared__ unsigned long long mbar[2];

    const int tid  = threadIdx.x;
    const int rank = blockIdx.x & 7;
    const int dir  = blockIdx.x >> 3;
    const float* xg  = dir ? xg_b  : xg_f;
    const float* whh = dir ? whh_b : whh_f;
    const int unit_base = rank * 32;

    const int p    = tid >> 1;       // pair index 0..127
    const int half = tid & 1;        // which half of h-dim this thread covers
    const int gate = p >> 5;         // 0..3 (i,f,g,o)
    const int jloc = p & 31;         // unit within this CTA
    const int row  = gate * 256 + unit_base + jloc;   // W_hh row

    // Load this thread's 128 weights into registers as 64 f32x2 pairs.
    unsigned long long w[64];
    {
        const ulonglong2* wg = (const ulonglong2*)(whh + (size_t)row * 256 + half * 128);
        #pragma unroll
        for (int i = 0; i < 32; i++) {
            ulonglong2 v = wg[i];
            w[2 * i] = v.x; w[2 * i + 1] = v.y;
        }
    }

    if (tid < 128) h_sh[0][tid] = 0ULL;
    if (tid < 2)   mbar_init(smaddr(&mbar[tid]), 256);
    __syncthreads();
    cluster_sync_();   // all mbarriers/h_sh[0] live before any remote traffic

    const uint32_t h_base  = smaddr(&h_sh[0][0]);
    const uint32_t mb_base = smaddr(&mbar[0]);

    const int t0 = dir ? (T_LEN - 1) : 0;
    const int dt = dir ? -1 : 1;

    float c_state = 0.f;   // valid for tid < 32
    float xg_cur = 0.f;
    if (!half) xg_cur = __ldg(&xg[(size_t)t0 * 1024 + row]);
    int ph0 = 0, ph1 = 0;

    for (int s = 0; s < T_LEN; s++) {
        const int t = t0 + s * dt;
        const int buf = s & 1;

        // prefetch next step's xg before blocking
        float xg_next = 0.f;
        if (!half && (s + 1 < T_LEN))
            xg_next = __ldg(&xg[(size_t)(t + dt) * 1024 + row]);

        if (s > 0) {
            uint32_t mb = mb_base + 8u * (uint32_t)buf;
            int par = buf ? ph1 : ph0;
            mbar_wait_cl(mb, (uint32_t)par);
            if (buf) ph1 ^= 1; else ph0 ^= 1;
        }

        // MAC: 64 packed FFMA2 against h in SMEM
        const ulonglong2* h2 = (const ulonglong2*)&h_sh[buf][half * 64];
        unsigned long long acc = 0ULL;
        #pragma unroll
        for (int i = 0; i < 32; i++) {
            ulonglong2 hv = h2[i];
            acc = ffma2(w[2 * i], hv.x, acc);
            acc = ffma2(w[2 * i + 1], hv.y, acc);
        }
        float2 af = *(float2*)&acc;
        float sum = af.x + af.y;
        sum += __shfl_down_sync(0xffffffffu, sum, 1);
        if (!half) gates_sh[p] = sum + xg_cur;
        __syncthreads();

        if (tid < 32) {
            const int j = tid;
            float iv = gates_sh[j];
            float fv = gates_sh[32 + j];
            float gv = gates_sh[64 + j];
            float ov = gates_sh[96 + j];
            c_state = sigm(fv) * c_state + sigm(iv) * tanh_fast(gv);
            float h = sigm(ov) * tanh_fast(c_state);

            h_out[(size_t)t * 512 + dir * 256 + unit_base + j] = h;

            const int slot = unit_base + j;   // 0..255 position in h vector
            const uint32_t off = (uint32_t)(((buf ^ 1) * 128 + (slot >> 1)) * 8 + (slot & 1) * 4);
            const uint32_t lmb = mb_base + 8u * (uint32_t)(buf ^ 1);
            #pragma unroll
            for (int r = 0; r < 8; r++) {
                uint32_t ra = mapa_sh(h_base + off, (uint32_t)r);
                uint32_t rm = mapa_sh(lmb, (uint32_t)r);
                remote_store_arrive(ra, h, rm);
            }
        }
        xg_cur = xg_next;
    }
    cluster_sync_();   // don't exit while peers' remote stores may target our SMEM
}

// =================================================================================
// Kernel 3: layer-1 input projection GEMM. xg[t][row] = h0[t](512) . w_ih_l1[row] + bias.
// C = A(T x 512) @ W^T(512 x 1024). BM=64, BN=64, BK=16, 256 threads, 4x4 per thread.
// grid (16, 512, 2).
// =================================================================================
__global__ void __launch_bounds__(256) xg1_gemm(
    const float* __restrict__ A,
    const float* __restrict__ Wf, const float* __restrict__ Wb,
    const float* __restrict__ bif, const float* __restrict__ bhf,
    const float* __restrict__ bib, const float* __restrict__ bhb,
    float* __restrict__ outf, float* __restrict__ outb)
{
    const float* W  = blockIdx.z ? Wb  : Wf;
    const float* bi = blockIdx.z ? bib : bif;
    const float* bh = blockIdx.z ? bhb : bhf;
    float* out      = blockIdx.z ? outb : outf;

    __shared__ float As[16][68];
    __shared__ float Bs[16][68];

    const int tid = threadIdx.x;
    const int tm = blockIdx.y * 64;   // t tile base
    const int cn = blockIdx.x * 64;   // col tile base
    const int tx = tid & 15;
    const int ty = tid >> 4;

    const int la_t = tid >> 2;          // 0..63
    const int la_k = (tid & 3) * 4;     // 0,4,8,12

    float acc[4][4] = {};

    for (int k0 = 0; k0 < 512; k0 += 16) {
        float4 av = *(const float4*)&A[(size_t)(tm + la_t) * 512 + k0 + la_k];
        float4 wv = *(const float4*)&W[(size_t)(cn + la_t) * 512 + k0 + la_k];
        __syncthreads();   // previous tile fully consumed
        As[la_k + 0][la_t] = av.x; As[la_k + 1][la_t] = av.y;
        As[la_k + 2][la_t] = av.z; As[la_k + 3][la_t] = av.w;
        Bs[la_k + 0][la_t] = wv.x; Bs[la_k + 1][la_t] = wv.y;
        Bs[la_k + 2][la_t] = wv.z; Bs[la_k + 3][la_t] = wv.w;
        __syncthreads();
        #pragma unroll
        for (int k = 0; k < 16; k++) {
            float a[4], b[4];
            #pragma unroll
            for (int i = 0; i < 4; i++) a[i] = As[k][ty * 4 + i];
            #pragma unroll
            for (int j = 0; j < 4; j++) b[j] = Bs[k][tx * 4 + j];
            #pragma unroll
            for (int i = 0; i < 4; i++)
                #pragma unroll
                for (int j = 0; j < 4; j++)
                    acc[i][j] += a[i] * b[j];
        }
    }

    float bias[4];
    #pragma unroll
    for (int j = 0; j < 4; j++)
        bias[j] = bi[cn + tx * 4 + j] + bh[cn + tx * 4 + j];
    #pragma unroll
    for (int i = 0; i < 4; i++)
        #pragma unroll
        for (int j = 0; j < 4; j++)
            out[(size_t)(tm + ty * 4 + i) * 1024 + cn + tx * 4 + j] = acc[i][j] + bias[j];
}

// =================================================================================
// Kernel 4: FC at inducing points + split output.
// out0[b][c] = h1[idx[b]] . fc[:, c]  (c < 32), out1 for c in [32,64).
// grid 1024, block 64.
// =================================================================================
__global__ void __launch_bounds__(64) fc_gather_kernel(
    const float* __restrict__ h1, const int* __restrict__ idx,
    const float* __restrict__ fc, float* __restrict__ out)
{
    __shared__ float hrow[512];
    const int b = blockIdx.x;
    const int t = idx[b];
    const int tid = threadIdx.x;
    for (int i = tid; i < 512; i += 64) hrow[i] = h1[(size_t)t * 512 + i];
    __syncthreads();
    float acc = 0.f;
    #pragma unroll 8
    for (int k = 0; k < 512; k++) acc += hrow[k] * fc[(size_t)k * 64 + tid];
    if (tid < 32) out[b * 32 + tid] = acc;
    else          out[NI_ * OUT_ + b * 32 + (tid - 32)] = acc;
}

// =================================================================================
// Launch
// =================================================================================
extern "C" void kernel_launch(void* const* d_in, const int* in_sizes, int n_in,
                              void* d_out, int out_size) {
    const float* Y        = (const float*)d_in[0];
    const float* dT       = (const float*)d_in[1];
    const int*   induce   = (const int*)  d_in[2];
    const float* w_ih_l0f = (const float*)d_in[3];
    const float* w_hh_l0f = (const float*)d_in[4];
    const float* b_ih_l0f = (const float*)d_in[5];
    const float* b_hh_l0f = (const float*)d_in[6];
    const float* w_ih_l0b = (const float*)d_in[7];
    const float* w_hh_l0b = (const float*)d_in[8];
    const float* b_ih_l0b = (const float*)d_in[9];
    const float* b_hh_l0b = (const float*)d_in[10];
    const float* w_ih_l1f = (const float*)d_in[11];
    const float* w_hh_l1f = (const float*)d_in[12];
    const float* b_ih_l1f = (const float*)d_in[13];
    const float* b_hh_l1f = (const float*)d_in[14];
    const float* w_ih_l1b = (const float*)d_in[15];
    const float* w_hh_l1b = (const float*)d_in[16];
    const float* b_ih_l1b = (const float*)d_in[17];
    const float* b_hh_l1b = (const float*)d_in[18];
    const float* fc_w     = (const float*)d_in[19];
    float* out = (float*)d_out;

    float *xg_f, *xg_b, *h0, *h1;
    cudaGetSymbolAddress((void**)&xg_f, g_xg_f);
    cudaGetSymbolAddress((void**)&xg_b, g_xg_b);
    cudaGetSymbolAddress((void**)&h0, g_h0);
    cudaGetSymbolAddress((void**)&h1, g_h1);

    // 1) layer-0 gate preactivations
    xg0_kernel<<<dim3(8, T_LEN / 32, 2), 256>>>(
        Y, dT,
        w_ih_l0f, b_ih_l0f, b_hh_l0f,
        w_ih_l0b, b_ih_l0b, b_hh_l0b,
        xg_f, xg_b);

    // cluster launch config for the scan
    cudaLaunchConfig_t cfg = {};
    cfg.gridDim  = dim3(16, 1, 1);
    cfg.blockDim = dim3(256, 1, 1);
    cfg.dynamicSmemBytes = 0;
    cfg.stream = 0;
    cudaLaunchAttribute attr[1];
    attr[0].id = cudaLaunchAttributeClusterDimension;
    attr[0].val.clusterDim.x = 8;
    attr[0].val.clusterDim.y = 1;
    attr[0].val.clusterDim.z = 1;
    cfg.attrs = attr;
    cfg.numAttrs = 1;

    // 2) layer-0 scan
    cudaLaunchKernelEx(&cfg, lstm_scan_kernel,
                       (const float*)xg_f, (const float*)xg_b,
                       w_hh_l0f, w_hh_l0b, h0);

    // 3) layer-1 gate preactivations (reuse xg buffers)
    xg1_gemm<<<dim3(16, T_LEN / 64, 2), 256>>>(
        (const float*)h0,
        w_ih_l1f, w_ih_l1b,
        b_ih_l1f, b_hh_l1f, b_ih_l1b, b_hh_l1b,
        xg_f, xg_b);

    // 4) layer-1 scan
    cudaLaunchKernelEx(&cfg, lstm_scan_kernel,
                       (const float*)xg_f, (const float*)xg_b,
                       w_hh_l1f, w_hh_l1b, h1);

    // 5) FC + gather
    fc_gather_kernel<<<NI_, 64>>>((const float*)h1, induce, fc_w, out);
}

// round 3
// speedup vs baseline: 1.4912x; 1.4912x over previous
#include <cuda_runtime.h>
#include <cuda_bf16.h>
#include <cstdint>

#define T_LEN 32768
#define HID   256
#define NI_   1024
#define OUT_  32

// ---------------- scratch (device globals: no allocation allowed) ----------------
__device__ float g_xg_f[(size_t)T_LEN * 1024];   // gate preacts, fwd dir (reused layer0/layer1)
__device__ float g_xg_b[(size_t)T_LEN * 1024];   // gate preacts, bwd dir
__device__ float g_h0[(size_t)T_LEN * 512];      // layer0 output [T, 2H]
__device__ float g_h1[(size_t)T_LEN * 512];      // layer1 output [T, 2H]

// ---------------- device helpers ----------------
__device__ __forceinline__ unsigned long long ffma2(unsigned long long a,
                                                    unsigned long long b,
                                                    unsigned long long c) {
    unsigned long long d;
    asm("fma.rn.f32x2 %0, %1, %2, %3;" : "=l"(d) : "l"(a), "l"(b), "l"(c));
    return d;
}

__device__ __forceinline__ float sigm(float x) { return 1.f / (1.f + __expf(-x)); }
__device__ __forceinline__ float tanh_fast(float x) {
    float a = fabsf(x);
    float e = __expf(-2.f * a);
    float t = (1.f - e) / (1.f + e);
    return copysignf(t, x);
}

__device__ __forceinline__ uint32_t smaddr(const void* p) {
    return (uint32_t)__cvta_generic_to_shared(p);
}
__device__ __forceinline__ void mbar_init(uint32_t a, uint32_t cnt) {
    asm volatile("mbarrier.init.shared.b64 [%0], %1;" :: "r"(a), "r"(cnt) : "memory");
}
__device__ __forceinline__ uint32_t mapa_sh(uint32_t a, uint32_t rank) {
    uint32_t r;
    asm("mapa.shared::cluster.u32 %0, %1, %2;" : "=r"(r) : "r"(a), "r"(rank));
    return r;
}
__device__ __forceinline__ void mbar_wait_cl(uint32_t addr, uint32_t parity) {
    asm volatile(
        "{\n\t.reg .pred P;\n"
        "LW_%=:\n\t"
        "mbarrier.try_wait.parity.acquire.cluster.shared::cta.b64 P, [%0], %1;\n\t"
        "@P bra LD_%=;\n\t"
        "bra LW_%=;\n"
        "LD_%=:\n\t}"
        :: "r"(addr), "r"(parity) : "memory");
}
__device__ __forceinline__ void cluster_sync_() {
    asm volatile("barrier.cluster.arrive.aligned;" ::: "memory");
    asm volatile("barrier.cluster.wait.aligned;" ::: "memory");
}

// =================================================================================
// Kernel 1: layer-0 input projection. xg[t][row] = x[t] . w_ih[row] + b_ih + b_hh
// =================================================================================
__global__ void __launch_bounds__(256) xg0_kernel(
    const float* __restrict__ Y, const float* __restrict__ dT,
    const float* __restrict__ w_f, const float* __restrict__ bi_f, const float* __restrict__ bh_f,
    const float* __restrict__ w_b, const float* __restrict__ bi_b, const float* __restrict__ bh_b,
    float* __restrict__ out_f, float* __restrict__ out_b)
{
    __shared__ float xs[32][64];
    __shared__ float ws[64][128];
    const float* w  = blockIdx.z ? w_b  : w_f;
    const float* bi = blockIdx.z ? bi_b : bi_f;
    const float* bh = blockIdx.z ? bh_b : bh_f;
    float* out      = blockIdx.z ? out_b : out_f;

    const int tid = threadIdx.x;
    const int tbase = blockIdx.y * 32;
    const int cbase = blockIdx.x * 128;

    for (int i = tid; i < 32 * 64; i += 256) {
        int tt = i >> 6, k = i & 63;
        int t = tbase + tt;
        xs[tt][k] = (k < 63) ? Y[(size_t)t * 63 + k] : dT[t];
    }
    for (int i = tid; i < 128 * 64; i += 256) {
        int c = i >> 6, k = i & 63;
        ws[k][c] = w[(size_t)(cbase + c) * 64 + k];
    }
    __syncthreads();

    const int c = tid & 127;
    const int tr0 = tid >> 7;
    const float bias = bi[cbase + c] + bh[cbase + c];
    for (int tt = tr0; tt < 32; tt += 2) {
        float acc = bias;
        #pragma unroll
        for (int k = 0; k < 64; k++) acc += xs[tt][k] * ws[k][c];
        out[(size_t)(tbase + tt) * 1024 + cbase + c] = acc;
    }
}

// =================================================================================
// Kernel 2: LSTM scan. 8-CTA cluster per direction (2 clusters). CTA `rank` owns
// hidden units [rank*32, rank*32+32) with register-resident W_hh rows.
// Per step: MAC vs SMEM h, gates on warp0, then the 8 WARP LEADERS each push the
// CTA's 128-B h slice to one peer rank (16x st.shared::cluster.b64) followed by a
// single release-arrive. Only 8 arrivals per mbarrier per step.
// =================================================================================
__global__ void __launch_bounds__(256, 1) lstm_scan_kernel(
    const float* __restrict__ xg_f, const float* __restrict__ xg_b,
    const float* __restrict__ whh_f, const float* __restrict__ whh_b,
    float* __restrict__ h_out)
{
    __shared__ __align__(16) unsigned long long h_sh[2][128]; // h as f32x2 pairs, double buffered
    __shared__ float gates_sh[128];
    __shared__ __align__(16) unsigned long long h_stage[16];  // this CTA's 32 h values
    __shared__ unsigned long long mbar[2];

    const int tid  = threadIdx.x;
    const int rank = blockIdx.x & 7;
    const int dir  = blockIdx.x >> 3;
    const float* xg  = dir ? xg_b  : xg_f;
    const float* whh = dir ? whh_b : whh_f;
    const int unit_base = rank * 32;

    const int p    = tid >> 1;       // pair index 0..127
    const int half = tid & 1;        // which half of h-dim this thread covers
    const int gate = p >> 5;         // 0..3 (i,f,g,o)
    const int jloc = p & 31;         // unit within this CTA
    const int row  = gate * 256 + unit_base + jloc;   // W_hh row

    // Load this thread's 128 weights into registers as 64 f32x2 pairs.
    unsigned long long w[64];
    {
        const ulonglong2* wg = (const ulonglong2*)(whh + (size_t)row * 256 + half * 128);
        #pragma unroll
        for (int i = 0; i < 32; i++) {
            ulonglong2 v = wg[i];
            w[2 * i] = v.x; w[2 * i + 1] = v.y;
        }
    }

    if (tid < 128) h_sh[0][tid] = 0ULL;
    if (tid < 2)   mbar_init(smaddr(&mbar[tid]), 8);   // 8 arrivals: one per source CTA
    __syncthreads();
    cluster_sync_();   // all mbarriers/h_sh[0] live before any remote traffic

    const uint32_t h_base  = smaddr(&h_sh[0][0]);
    const uint32_t mb_base = smaddr(&mbar[0]);

    // Warp leader `wid` sends this CTA's slice to rank `wid`. Precompute peer addrs.
    const int wid = tid >> 5;
    uint32_t peer_h = 0, peer_mb = 0;
    if ((tid & 31) == 0) {
        peer_h  = mapa_sh(h_base, (uint32_t)wid) + (uint32_t)unit_base * 4u;
        peer_mb = mapa_sh(mb_base, (uint32_t)wid);
    }

    const int t0 = dir ? (T_LEN - 1) : 0;
    const int dt = dir ? -1 : 1;

    float c_state = 0.f;   // valid for tid < 32
    float xg_cur = 0.f;
    if (!half) xg_cur = __ldg(&xg[(size_t)t0 * 1024 + row]);
    int ph0 = 0, ph1 = 0;

    for (int s = 0; s < T_LEN; s++) {
        const int t = t0 + s * dt;
        const int buf = s & 1;

        // prefetch next step's xg before blocking
        float xg_next = 0.f;
        if (!half && (s + 1 < T_LEN))
            xg_next = __ldg(&xg[(size_t)(t + dt) * 1024 + row]);

        if (s > 0) {
            uint32_t mb = mb_base + 8u * (uint32_t)buf;
            int par = buf ? ph1 : ph0;
            mbar_wait_cl(mb, (uint32_t)par);
            if (buf) ph1 ^= 1; else ph0 ^= 1;
        }

        // MAC: 64 packed FFMA2 against h in SMEM, 2 accumulator chains
        const ulonglong2* h2 = (const ulonglong2*)&h_sh[buf][half * 64];
        unsigned long long acc0 = 0ULL, acc1 = 0ULL;
        #pragma unroll
        for (int i = 0; i < 16; i++) {
            ulonglong2 ha = h2[2 * i];
            ulonglong2 hb = h2[2 * i + 1];
            acc0 = ffma2(w[4 * i + 0], ha.x, acc0);
            acc1 = ffma2(w[4 * i + 1], ha.y, acc1);
            acc0 = ffma2(w[4 * i + 2], hb.x, acc0);
            acc1 = ffma2(w[4 * i + 3], hb.y, acc1);
        }
        float2 a0 = *(float2*)&acc0;
        float2 a1 = *(float2*)&acc1;
        float sum = (a0.x + a0.y) + (a1.x + a1.y);
        sum += __shfl_down_sync(0xffffffffu, sum, 1);
        if (!half) gates_sh[p] = sum + xg_cur;
        __syncthreads();

        if (tid < 32) {
            const int j = tid;
            float iv = gates_sh[j];
            float fv = gates_sh[32 + j];
            float gv = gates_sh[64 + j];
            float ov = gates_sh[96 + j];
            c_state = sigm(fv) * c_state + sigm(iv) * tanh_fast(gv);
            float h = sigm(ov) * tanh_fast(c_state);

            h_out[(size_t)t * 512 + dir * 256 + unit_base + j] = h;
            ((float*)h_stage)[j] = h;
        }
        __syncthreads();

        // 8 warp leaders: push 128-B slice to peer `wid`, then single release-arrive.
        if ((tid & 31) == 0) {
            const uint32_t dst = peer_h + (uint32_t)((buf ^ 1) * 1024);
            #pragma unroll
            for (int i = 0; i < 16; i++) {
                unsigned long long v = h_stage[i];
                asm volatile("st.shared::cluster.b64 [%0], %1;"
                             :: "r"(dst + (uint32_t)(i * 8)), "l"(v) : "memory");
            }
            asm volatile("mbarrier.arrive.release.cluster.shared::cluster.b64 _, [%0];"
                         :: "r"(peer_mb + 8u * (uint32_t)(buf ^ 1)) : "memory");
        }
        xg_cur = xg_next;
    }
    cluster_sync_();   // don't exit while peers' remote stores may target our SMEM
}

// =================================================================================
// Kernel 3: layer-1 input projection GEMM. BM=64, BN=64, BK=16, 256 threads.
// =================================================================================
__global__ void __launch_bounds__(256) xg1_gemm(
    const float* __restrict__ A,
    const float* __restrict__ Wf, const float* __restrict__ Wb,
    const float* __restrict__ bif, const float* __restrict__ bhf,
    const float* __restrict__ bib, const float* __restrict__ bhb,
    float* __restrict__ outf, float* __restrict__ outb)
{
    const float* W  = blockIdx.z ? Wb  : Wf;
    const float* bi = blockIdx.z ? bib : bif;
    const float* bh = blockIdx.z ? bhb : bhf;
    float* out      = blockIdx.z ? outb : outf;

    __shared__ float As[16][68];
    __shared__ float Bs[16][68];

    const int tid = threadIdx.x;
    const int tm = blockIdx.y * 64;
    const int cn = blockIdx.x * 64;
    const int tx = tid & 15;
    const int ty = tid >> 4;

    const int la_t = tid >> 2;
    const int la_k = (tid & 3) * 4;

    float acc[4][4] = {};

    for (int k0 = 0; k0 < 512; k0 += 16) {
        float4 av = *(const float4*)&A[(size_t)(tm + la_t) * 512 + k0 + la_k];
        float4 wv = *(const float4*)&W[(size_t)(cn + la_t) * 512 + k0 + la_k];
        __syncthreads();
        As[la_k + 0][la_t] = av.x; As[la_k + 1][la_t] = av.y;
        As[la_k + 2][la_t] = av.z; As[la_k + 3][la_t] = av.w;
        Bs[la_k + 0][la_t] = wv.x; Bs[la_k + 1][la_t] = wv.y;
        Bs[la_k + 2][la_t] = wv.z; Bs[la_k + 3][la_t] = wv.w;
        __syncthreads();
        #pragma unroll
        for (int k = 0; k < 16; k++) {
            float a[4], b[4];
            #pragma unroll
            for (int i = 0; i < 4; i++) a[i] = As[k][ty * 4 + i];
            #pragma unroll
            for (int j = 0; j < 4; j++) b[j] = Bs[k][tx * 4 + j];
            #pragma unroll
            for (int i = 0; i < 4; i++)
                #pragma unroll
                for (int j = 0; j < 4; j++)
                    acc[i][j] += a[i] * b[j];
        }
    }

    float bias[4];
    #pragma unroll
    for (int j = 0; j < 4; j++)
        bias[j] = bi[cn + tx * 4 + j] + bh[cn + tx * 4 + j];
    #pragma unroll
    for (int i = 0; i < 4; i++)
        #pragma unroll
        for (int j = 0; j < 4; j++)
            out[(size_t)(tm + ty * 4 + i) * 1024 + cn + tx * 4 + j] = acc[i][j] + bias[j];
}

// =================================================================================
// Kernel 4: FC at inducing points + split output.
// =================================================================================
__global__ void __launch_bounds__(64) fc_gather_kernel(
    const float* __restrict__ h1, const int* __restrict__ idx,
    const float* __restrict__ fc, float* __restrict__ out)
{
    __shared__ float hrow[512];
    const int b = blockIdx.x;
    const int t = idx[b];
    const int tid = threadIdx.x;
    for (int i = tid; i < 512; i += 64) hrow[i] = h1[(size_t)t * 512 + i];
    __syncthreads();
    float acc = 0.f;
    #pragma unroll 8
    for (int k = 0; k < 512; k++) acc += hrow[k] * fc[(size_t)k * 64 + tid];
    if (tid < 32) out[b * 32 + tid] = acc;
    else          out[NI_ * OUT_ + b * 32 + (tid - 32)] = acc;
}

// =================================================================================
// Launch
// =================================================================================
extern "C" void kernel_launch(void* const* d_in, const int* in_sizes, int n_in,
                              void* d_out, int out_size) {
    const float* Y        = (const float*)d_in[0];
    const float* dT       = (const float*)d_in[1];
    const int*   induce   = (const int*)  d_in[2];
    const float* w_ih_l0f = (const float*)d_in[3];
    const float* w_hh_l0f = (const float*)d_in[4];
    const float* b_ih_l0f = (const float*)d_in[5];
    const float* b_hh_l0f = (const float*)d_in[6];
    const float* w_ih_l0b = (const float*)d_in[7];
    const float* w_hh_l0b = (const float*)d_in[8];
    const float* b_ih_l0b = (const float*)d_in[9];
    const float* b_hh_l0b = (const float*)d_in[10];
    const float* w_ih_l1f = (const float*)d_in[11];
    const float* w_hh_l1f = (const float*)d_in[12];
    const float* b_ih_l1f = (const float*)d_in[13];
    const float* b_hh_l1f = (const float*)d_in[14];
    const float* w_ih_l1b = (const float*)d_in[15];
    const float* w_hh_l1b = (const float*)d_in[16];
    const float* b_ih_l1b = (const float*)d_in[17];
    const float* b_hh_l1b = (const float*)d_in[18];
    const float* fc_w     = (const float*)d_in[19];
    float* out = (float*)d_out;

    float *xg_f, *xg_b, *h0, *h1;
    cudaGetSymbolAddress((void**)&xg_f, g_xg_f);
    cudaGetSymbolAddress((void**)&xg_b, g_xg_b);
    cudaGetSymbolAddress((void**)&h0, g_h0);
    cudaGetSymbolAddress((void**)&h1, g_h1);

    // 1) layer-0 gate preactivations
    xg0_kernel<<<dim3(8, T_LEN / 32, 2), 256>>>(
        Y, dT,
        w_ih_l0f, b_ih_l0f, b_hh_l0f,
        w_ih_l0b, b_ih_l0b, b_hh_l0b,
        xg_f, xg_b);

    // cluster launch config for the scan
    cudaLaunchConfig_t cfg = {};
    cfg.gridDim  = dim3(16, 1, 1);
    cfg.blockDim = dim3(256, 1, 1);
    cfg.dynamicSmemBytes = 0;
    cfg.stream = 0;
    cudaLaunchAttribute attr[1];
    attr[0].id = cudaLaunchAttributeClusterDimension;
    attr[0].val.clusterDim.x = 8;
    attr[0].val.clusterDim.y = 1;
    attr[0].val.clusterDim.z = 1;
    cfg.attrs = attr;
    cfg.numAttrs = 1;

    // 2) layer-0 scan
    cudaLaunchKernelEx(&cfg, lstm_scan_kernel,
                       (const float*)xg_f, (const float*)xg_b,
                       w_hh_l0f, w_hh_l0b, h0);

    // 3) layer-1 gate preactivations (reuse xg buffers)
    xg1_gemm<<<dim3(16, T_LEN / 64, 2), 256>>>(
        (const float*)h0,
        w_ih_l1f, w_ih_l1b,
        b_ih_l1f, b_hh_l1f, b_ih_l1b, b_hh_l1b,
        xg_f, xg_b);

    // 4) layer-1 scan
    cudaLaunchKernelEx(&cfg, lstm_scan_kernel,
                       (const float*)xg_f, (const float*)xg_b,
                       w_hh_l1f, w_hh_l1b, h1);

    // 5) FC + gather
    fc_gather_kernel<<<NI_, 64>>>((const float*)h1, induce, fc_w, out);
}

// round 5
// speedup vs baseline: 1.6212x; 1.0872x over previous
#include <cuda_runtime.h>
#include <cuda_bf16.h>
#include <cstdint>

#define T_LEN 32768
#define HID   256
#define NI_   1024
#define OUT_  32

// ---------------- scratch (device globals: no allocation allowed) ----------------
__device__ float g_xg_f[(size_t)T_LEN * 1024];   // gate preacts, fwd dir (reused layer0/layer1)
__device__ float g_xg_b[(size_t)T_LEN * 1024];   // gate preacts, bwd dir
__device__ float g_h0[(size_t)T_LEN * 512];      // layer0 output [T, 2H]
__device__ float g_h1[(size_t)T_LEN * 512];      // layer1 output [T, 2H]

// ---------------- device helpers ----------------
__device__ __forceinline__ unsigned long long ffma2(unsigned long long a,
                                                    unsigned long long b,
                                                    unsigned long long c) {
    unsigned long long d;
    asm("fma.rn.f32x2 %0, %1, %2, %3;" : "=l"(d) : "l"(a), "l"(b), "l"(c));
    return d;
}

__device__ __forceinline__ uint32_t smaddr(const void* p) {
    return (uint32_t)__cvta_generic_to_shared(p);
}
__device__ __forceinline__ void mbar_init(uint32_t a, uint32_t cnt) {
    asm volatile("mbarrier.init.shared.b64 [%0], %1;" :: "r"(a), "r"(cnt) : "memory");
}
__device__ __forceinline__ uint32_t mapa_sh(uint32_t a, uint32_t rank) {
    uint32_t r;
    asm("mapa.shared::cluster.u32 %0, %1, %2;" : "=r"(r) : "r"(a), "r"(rank));
    return r;
}
__device__ __forceinline__ void mbar_wait_cl(uint32_t addr, uint32_t parity) {
    asm volatile(
        "{\n\t.reg .pred P;\n"
        "LW_%=:\n\t"
        "mbarrier.try_wait.parity.acquire.cluster.shared::cta.b64 P, [%0], %1;\n\t"
        "@P bra LD_%=;\n\t"
        "bra LW_%=;\n"
        "LD_%=:\n\t}"
        :: "r"(addr), "r"(parity) : "memory");
}
__device__ __forceinline__ void cluster_sync_() {
    asm volatile("barrier.cluster.arrive.aligned;" ::: "memory");
    asm volatile("barrier.cluster.wait.aligned;" ::: "memory");
}

// =================================================================================
// Kernel 1: layer-0 input projection. xg[t][row] = x[t] . w_ih[row] + b_ih + b_hh
// =================================================================================
__global__ void __launch_bounds__(256) xg0_kernel(
    const float* __restrict__ Y, const float* __restrict__ dT,
    const float* __restrict__ w_f, const float* __restrict__ bi_f, const float* __restrict__ bh_f,
    const float* __restrict__ w_b, const float* __restrict__ bi_b, const float* __restrict__ bh_b,
    float* __restrict__ out_f, float* __restrict__ out_b)
{
    __shared__ float xs[32][64];
    __shared__ float ws[64][128];
    const float* w  = blockIdx.z ? w_b  : w_f;
    const float* bi = blockIdx.z ? bi_b : bi_f;
    const float* bh = blockIdx.z ? bh_b : bh_f;
    float* out      = blockIdx.z ? out_b : out_f;

    const int tid = threadIdx.x;
    const int tbase = blockIdx.y * 32;
    const int cbase = blockIdx.x * 128;

    for (int i = tid; i < 32 * 64; i += 256) {
        int tt = i >> 6, k = i & 63;
        int t = tbase + tt;
        xs[tt][k] = (k < 63) ? Y[(size_t)t * 63 + k] : dT[t];
    }
    for (int i = tid; i < 128 * 64; i += 256) {
        int c = i >> 6, k = i & 63;
        ws[k][c] = w[(size_t)(cbase + c) * 64 + k];
    }
    __syncthreads();

    const int c = tid & 127;
    const int tr0 = tid >> 7;
    const float bias = bi[cbase + c] + bh[cbase + c];
    for (int tt = tr0; tt < 32; tt += 2) {
        float acc = bias;
        #pragma unroll
        for (int k = 0; k < 64; k++) acc += xs[tt][k] * ws[k][c];
        out[(size_t)(tbase + tt) * 1024 + cbase + c] = acc;
    }
}

// =================================================================================
// Kernel 2: LSTM scan. 8-CTA cluster per direction (2 clusters, grid 16).
// CTA `rank` owns hidden units [rank*32, +32), W_hh rows register-resident.
// Sync protocol (PROVEN, R3): per step the 8 warp leaders each push the CTA's
// 128-B h slice to one peer rank (16x st.shared::cluster.b64) + single
// release-arrive on the peer's double-buffered mbarrier (8 arrivals each).
// NEW: only lane 0 of each warp polls try_wait (acquire), then __syncwarp —
// cuts mbarrier polling contention 256 -> 8 threads.
// NEW: gate math uses __fdividef (MUFU.RCP) instead of div.rn.
// =================================================================================
__global__ void __launch_bounds__(256, 1) lstm_scan_kernel(
    const float* __restrict__ xg_f, const float* __restrict__ xg_b,
    const float* __restrict__ whh_f, const float* __restrict__ whh_b,
    float* __restrict__ h_out)
{
    __shared__ __align__(16) unsigned long long h_sh[2][128]; // h as f32x2 pairs, double buffered
    __shared__ float gates_sh[128];
    __shared__ __align__(16) unsigned long long h_stage[16];  // this CTA's 32 h values
    __shared__ unsigned long long mbar[2];

    const int tid  = threadIdx.x;
    const int rank = blockIdx.x & 7;
    const int dir  = blockIdx.x >> 3;
    const float* xg  = dir ? xg_b  : xg_f;
    const float* whh = dir ? whh_b : whh_f;
    const int unit_base = rank * 32;

    const int p    = tid >> 1;       // pair index 0..127
    const int half = tid & 1;        // which half of h-dim this thread covers
    const int gate = p >> 5;         // 0..3 (i,f,g,o)
    const int jloc = p & 31;         // unit within this CTA
    const int row  = gate * 256 + unit_base + jloc;   // W_hh row

    // Load this thread's 128 weights into registers as 64 f32x2 pairs.
    unsigned long long w[64];
    {
        const ulonglong2* wg = (const ulonglong2*)(whh + (size_t)row * 256 + half * 128);
        #pragma unroll
        for (int i = 0; i < 32; i++) {
            ulonglong2 v = wg[i];
            w[2 * i] = v.x; w[2 * i + 1] = v.y;
        }
    }

    if (tid < 128) h_sh[0][tid] = 0ULL;
    if (tid < 2)   mbar_init(smaddr(&mbar[tid]), 8);   // 8 arrivals: one per source CTA
    __syncthreads();
    cluster_sync_();   // all mbarriers/h_sh[0] live before any remote traffic

    const uint32_t h_base  = smaddr(&h_sh[0][0]);
    const uint32_t mb_base = smaddr(&mbar[0]);

    // Warp leader `wid` sends this CTA's slice to rank `wid`. Precompute peer addrs.
    const int wid = tid >> 5;
    const int lane = tid & 31;
    uint32_t peer_h = 0, peer_mb = 0;
    if (lane == 0) {
        peer_h  = mapa_sh(h_base, (uint32_t)wid) + (uint32_t)unit_base * 4u;
        peer_mb = mapa_sh(mb_base, (uint32_t)wid);
    }

    const int t0 = dir ? (T_LEN - 1) : 0;
    const int dt = dir ? -1 : 1;

    float c_state = 0.f;   // valid for tid < 32
    float xg_cur = 0.f, xg_nxt = 0.f;
    if (!half) {
        xg_cur = __ldg(&xg[(size_t)t0 * 1024 + row]);
        xg_nxt = __ldg(&xg[(size_t)(t0 + dt) * 1024 + row]);
    }
    int ph0 = 0, ph1 = 0;

    for (int s = 0; s < T_LEN; s++) {
        const int t = t0 + s * dt;
        const int buf = s & 1;

        // prefetch xg for step s+2 before blocking
        float xg_n2 = 0.f;
        if (!half && (s + 2 < T_LEN))
            xg_n2 = __ldg(&xg[(size_t)(t + 2 * dt) * 1024 + row]);

        if (s > 0) {
            uint32_t mb = mb_base + 8u * (uint32_t)buf;
            int par = buf ? ph1 : ph0;
            if (lane == 0) mbar_wait_cl(mb, (uint32_t)par);  // single poller per warp
            __syncwarp();
            if (buf) ph1 ^= 1; else ph0 ^= 1;
        }

        // MAC: 64 packed FFMA2 against h in SMEM, 2 accumulator chains
        const ulonglong2* h2 = (const ulonglong2*)&h_sh[buf][half * 64];
        unsigned long long acc0 = 0ULL, acc1 = 0ULL;
        #pragma unroll
        for (int i = 0; i < 16; i++) {
            ulonglong2 ha = h2[2 * i];
            ulonglong2 hb = h2[2 * i + 1];
            acc0 = ffma2(w[4 * i + 0], ha.x, acc0);
            acc1 = ffma2(w[4 * i + 1], ha.y, acc1);
            acc0 = ffma2(w[4 * i + 2], hb.x, acc0);
            acc1 = ffma2(w[4 * i + 3], hb.y, acc1);
        }
        float2 a0 = *(float2*)&acc0;
        float2 a1 = *(float2*)&acc1;
        float sum = (a0.x + a0.y) + (a1.x + a1.y);
        sum += __shfl_down_sync(0xffffffffu, sum, 1);
        if (!half) gates_sh[p] = sum + xg_cur;
        __syncthreads();

        if (tid < 32) {
            const int j = tid;
            float iv = gates_sh[j];
            float fv = gates_sh[32 + j];
            float gv = gates_sh[64 + j];
            float ov = gates_sh[96 + j];
            // fast gates: MUFU.EX2 + MUFU.RCP paths (~2 ulp), ILP across 4 gates
            float ei = __expf(-iv), ef = __expf(-fv), eo = __expf(-ov);
            float eg = __expf(-2.f * fabsf(gv));
            float si = __fdividef(1.f, 1.f + ei);
            float sf = __fdividef(1.f, 1.f + ef);
            float so = __fdividef(1.f, 1.f + eo);
            float tg = copysignf(__fdividef(1.f - eg, 1.f + eg), gv);
            c_state = sf * c_state + si * tg;
            float ec = __expf(-2.f * fabsf(c_state));
            float tc = copysignf(__fdividef(1.f - ec, 1.f + ec), c_state);
            float h = so * tc;

            h_out[(size_t)t * 512 + dir * 256 + unit_base + j] = h;
            ((float*)h_stage)[j] = h;
        }
        __syncthreads();

        // 8 warp leaders: push 128-B slice to peer `wid`, then single release-arrive.
        if (lane == 0) {
            const uint32_t dst = peer_h + (uint32_t)((buf ^ 1) * 1024);
            #pragma unroll
            for (int i = 0; i < 16; i++) {
                unsigned long long v = h_stage[i];
                asm volatile("st.shared::cluster.b64 [%0], %1;"
                             :: "r"(dst + (uint32_t)(i * 8)), "l"(v) : "memory");
            }
            asm volatile("mbarrier.arrive.release.cluster.shared::cluster.b64 _, [%0];"
                         :: "r"(peer_mb + 8u * (uint32_t)(buf ^ 1)) : "memory");
        }
        xg_cur = xg_nxt;
        xg_nxt = xg_n2;
    }
    cluster_sync_();   // don't exit while peers' remote stores may target our SMEM
}

// =================================================================================
// Kernel 3: layer-1 input projection GEMM. BM=64, BN=64, BK=16, 256 threads.
// =================================================================================
__global__ void __launch_bounds__(256) xg1_gemm(
    const float* __restrict__ A,
    const float* __restrict__ Wf, const float* __restrict__ Wb,
    const float* __restrict__ bif, const float* __restrict__ bhf,
    const float* __restrict__ bib, const float* __restrict__ bhb,
    float* __restrict__ outf, float* __restrict__ outb)
{
    const float* W  = blockIdx.z ? Wb  : Wf;
    const float* bi = blockIdx.z ? bib : bif;
    const float* bh = blockIdx.z ? bhb : bhf;
    float* out      = blockIdx.z ? outb : outf;

    __shared__ float As[16][68];
    __shared__ float Bs[16][68];

    const int tid = threadIdx.x;
    const int tm = blockIdx.y * 64;
    const int cn = blockIdx.x * 64;
    const int tx = tid & 15;
    const int ty = tid >> 4;

    const int la_t = tid >> 2;
    const int la_k = (tid & 3) * 4;

    float acc[4][4] = {};

    for (int k0 = 0; k0 < 512; k0 += 16) {
        float4 av = *(const float4*)&A[(size_t)(tm + la_t) * 512 + k0 + la_k];
        float4 wv = *(const float4*)&W[(size_t)(cn + la_t) * 512 + k0 + la_k];
        __syncthreads();
        As[la_k + 0][la_t] = av.x; As[la_k + 1][la_t] = av.y;
        As[la_k + 2][la_t] = av.z; As[la_k + 3][la_t] = av.w;
        Bs[la_k + 0][la_t] = wv.x; Bs[la_k + 1][la_t] = wv.y;
        Bs[la_k + 2][la_t] = wv.z; Bs[la_k + 3][la_t] = wv.w;
        __syncthreads();
        #pragma unroll
        for (int k = 0; k < 16; k++) {
            float a[4], b[4];
            #pragma unroll
            for (int i = 0; i < 4; i++) a[i] = As[k][ty * 4 + i];
            #pragma unroll
            for (int j = 0; j < 4; j++) b[j] = Bs[k][tx * 4 + j];
            #pragma unroll
            for (int i = 0; i < 4; i++)
                #pragma unroll
                for (int j = 0; j < 4; j++)
                    acc[i][j] += a[i] * b[j];
        }
    }

    float bias[4];
    #pragma unroll
    for (int j = 0; j < 4; j++)
        bias[j] = bi[cn + tx * 4 + j] + bh[cn + tx * 4 + j];
    #pragma unroll
    for (int i = 0; i < 4; i++)
        #pragma unroll
        for (int j = 0; j < 4; j++)
            out[(size_t)(tm + ty * 4 + i) * 1024 + cn + tx * 4 + j] = acc[i][j] + bias[j];
}

// =================================================================================
// Kernel 4: FC at inducing points + split output.
// =================================================================================
__global__ void __launch_bounds__(64) fc_gather_kernel(
    const float* __restrict__ h1, const int* __restrict__ idx,
    const float* __restrict__ fc, float* __restrict__ out)
{
    __shared__ float hrow[512];
    const int b = blockIdx.x;
    const int t = idx[b];
    const int tid = threadIdx.x;
    for (int i = tid; i < 512; i += 64) hrow[i] = h1[(size_t)t * 512 + i];
    __syncthreads();
    float acc = 0.f;
    #pragma unroll 8
    for (int k = 0; k < 512; k++) acc += hrow[k] * fc[(size_t)k * 64 + tid];
    if (tid < 32) out[b * 32 + tid] = acc;
    else          out[NI_ * OUT_ + b * 32 + (tid - 32)] = acc;
}

// =================================================================================
// Launch
// =================================================================================
extern "C" void kernel_launch(void* const* d_in, const int* in_sizes, int n_in,
                              void* d_out, int out_size) {
    const float* Y        = (const float*)d_in[0];
    const float* dT       = (const float*)d_in[1];
    const int*   induce   = (const int*)  d_in[2];
    const float* w_ih_l0f = (const float*)d_in[3];
    const float* w_hh_l0f = (const float*)d_in[4];
    const float* b_ih_l0f = (const float*)d_in[5];
    const float* b_hh_l0f = (const float*)d_in[6];
    const float* w_ih_l0b = (const float*)d_in[7];
    const float* w_hh_l0b = (const float*)d_in[8];
    const float* b_ih_l0b = (const float*)d_in[9];
    const float* b_hh_l0b = (const float*)d_in[10];
    const float* w_ih_l1f = (const float*)d_in[11];
    const float* w_hh_l1f = (const float*)d_in[12];
    const float* b_ih_l1f = (const float*)d_in[13];
    const float* b_hh_l1f = (const float*)d_in[14];
    const float* w_ih_l1b = (const float*)d_in[15];
    const float* w_hh_l1b = (const float*)d_in[16];
    const float* b_ih_l1b = (const float*)d_in[17];
    const float* b_hh_l1b = (const float*)d_in[18];
    const float* fc_w     = (const float*)d_in[19];
    float* out = (float*)d_out;

    float *xg_f, *xg_b, *h0, *h1;
    cudaGetSymbolAddress((void**)&xg_f, g_xg_f);
    cudaGetSymbolAddress((void**)&xg_b, g_xg_b);
    cudaGetSymbolAddress((void**)&h0, g_h0);
    cudaGetSymbolAddress((void**)&h1, g_h1);

    // 1) layer-0 gate preactivations
    xg0_kernel<<<dim3(8, T_LEN / 32, 2), 256>>>(
        Y, dT,
        w_ih_l0f, b_ih_l0f, b_hh_l0f,
        w_ih_l0b, b_ih_l0b, b_hh_l0b,
        xg_f, xg_b);

    // cluster launch config for the scan
    cudaLaunchConfig_t cfg = {};
    cfg.gridDim  = dim3(16, 1, 1);
    cfg.blockDim = dim3(256, 1, 1);
    cfg.dynamicSmemBytes = 0;
    cfg.stream = 0;
    cudaLaunchAttribute attr[1];
    attr[0].id = cudaLaunchAttributeClusterDimension;
    attr[0].val.clusterDim.x = 8;
    attr[0].val.clusterDim.y = 1;
    attr[0].val.clusterDim.z = 1;
    cfg.attrs = attr;
    cfg.numAttrs = 1;

    // 2) layer-0 scan
    cudaLaunchKernelEx(&cfg, lstm_scan_kernel,
                       (const float*)xg_f, (const float*)xg_b,
                       w_hh_l0f, w_hh_l0b, h0);

    // 3) layer-1 gate preactivations (reuse xg buffers)
    xg1_gemm<<<dim3(16, T_LEN / 64, 2), 256>>>(
        (const float*)h0,
        w_ih_l1f, w_ih_l1b,
        b_ih_l1f, b_hh_l1f, b_ih_l1b, b_hh_l1b,
        xg_f, xg_b);

    // 4) layer-1 scan
    cudaLaunchKernelEx(&cfg, lstm_scan_kernel,
                       (const float*)xg_f, (const float*)xg_b,
                       w_hh_l1f, w_hh_l1b, h1);

    // 5) FC + gather
    fc_gather_kernel<<<NI_, 64>>>((const float*)h1, induce, fc_w, out);
}